// round 4
// baseline (speedup 1.0000x reference)
#include <cuda_runtime.h>
#include <cuda_bf16.h>
#include <cstdint>

#define DIM     64
#define KMAX    1024
#define TM      256          // rows per CTA
#define THREADS 256          // 8 warps
#define CAP     28           // candidate cap per row
#define ROWB    72           // ushorts per padded row (144 B: 9x16B -> conflict-free ldmatrix)
#define ROWU    36           // uints per padded row

// ---------------- device globals (prep results) ----------------
__device__ float g_c2[KMAX];
__device__ unsigned int g_cmaxU;                       // asuint(max_k ||c_k||), monotone
__device__ __align__(16) unsigned short g_cbB[KMAX * ROWB];   // bf16 codebook, padded rows

// ---------------- smem layout (byte offsets, all 16-mult) ----------------
#define OFF_CB    0            // 1024*144  = 147456
#define OFF_A     147456       // 256*144   =  36864
#define OFF_C2    184320       // 1024*4    =   4096
#define OFF_R2    188416       // 256*4     =   1024
#define OFF_RMIN  189440       // 256*4     =   1024
#define OFF_CNT   190464       // 256*4     =   1024
#define OFF_CAND  191488       // 256*28*4  =  28672
#define SMEM_DYN  220160

__device__ __forceinline__ uint32_t smem_u32(const void* p) {
    uint32_t a;
    asm("{ .reg .u64 t; cvta.to.shared.u64 t, %1; cvt.u32.u64 %0, t; }"
        : "=r"(a) : "l"(p));
    return a;
}
// order-preserving float<->uint (total order incl. negatives)
__device__ __forceinline__ unsigned int encf(float f) {
    unsigned int u = __float_as_uint(f);
    return (u & 0x80000000u) ? ~u : (u | 0x80000000u);
}
__device__ __forceinline__ float decf(unsigned int u) {
    return (u & 0x80000000u) ? __uint_as_float(u & 0x7FFFFFFFu)
                             : __uint_as_float(~u);
}

// ---------------- prep: c2 (R1-exact), bf16 codebook (padded), max ||c|| ----------------
__global__ void prep_kernel(const float* __restrict__ cb, int K) {
    int k = blockIdx.x * blockDim.x + threadIdx.x;
    if (k >= K) return;
    const float4* row = reinterpret_cast<const float4*>(cb + (size_t)k * DIM);
    float vals[DIM];
    float p0 = 0.f, p1 = 0.f, p2 = 0.f, p3 = 0.f;
#pragma unroll
    for (int j = 0; j < 16; j += 4) {
        float4 a = row[j + 0];
        float4 b = row[j + 1];
        float4 c = row[j + 2];
        float4 d = row[j + 3];
        p0 += a.x * a.x + a.y * a.y + a.z * a.z + a.w * a.w;
        p1 += b.x * b.x + b.y * b.y + b.z * b.z + b.w * b.w;
        p2 += c.x * c.x + c.y * c.y + c.z * c.z + c.w * c.w;
        p3 += d.x * d.x + d.y * d.y + d.z * d.z + d.w * d.w;
        vals[4*(j+0)+0]=a.x; vals[4*(j+0)+1]=a.y; vals[4*(j+0)+2]=a.z; vals[4*(j+0)+3]=a.w;
        vals[4*(j+1)+0]=b.x; vals[4*(j+1)+1]=b.y; vals[4*(j+1)+2]=b.z; vals[4*(j+1)+3]=b.w;
        vals[4*(j+2)+0]=c.x; vals[4*(j+2)+1]=c.y; vals[4*(j+2)+2]=c.z; vals[4*(j+2)+3]=c.w;
        vals[4*(j+3)+0]=d.x; vals[4*(j+3)+1]=d.y; vals[4*(j+3)+2]=d.z; vals[4*(j+3)+3]=d.w;
    }
    float c2 = (p0 + p1) + (p2 + p3);
    g_c2[k] = c2;
    atomicMax(&g_cmaxU, __float_as_uint(sqrtf(c2)));   // positive floats: asuint monotone
#pragma unroll
    for (int c = 0; c < DIM; c++) {
        __nv_bfloat16 h = __float2bfloat16(vals[c]);
        g_cbB[(size_t)k * ROWB + c] = *reinterpret_cast<unsigned short*>(&h);
    }
#pragma unroll
    for (int c = DIM; c < ROWB; c++) g_cbB[(size_t)k * ROWB + c] = 0;
}

// ---------------- main: bf16 HMMA scan + guaranteed-superset candidates + exact recheck ----------------
__global__ __launch_bounds__(THREADS, 1)
void vq_main(const float* __restrict__ residual,
             const float* __restrict__ cb,
             float* __restrict__ qout,
             float* __restrict__ codes,
             int N, int K, int wq, int wc)
{
    extern __shared__ __align__(16) unsigned char dsm[];
    const uint32_t sb = smem_u32(dsm);

    float*        sC2   = (float*)(dsm + OFF_C2);
    float*        sR2   = (float*)(dsm + OFF_R2);
    unsigned int* sRMIN = (unsigned int*)(dsm + OFF_RMIN);
    int*          sCNT  = (int*)(dsm + OFF_CNT);
    int*          sCand = (int*)(dsm + OFF_CAND);

    const int tid  = threadIdx.x;
    const int lane = tid & 31;
    const int warp = tid >> 5;
    const int m0   = blockIdx.x * TM;
    const int rows = (N - m0 < TM) ? (N - m0) : TM;

    // --- codebook bf16 tile copy (pre-padded image, uint4) ---
    {
        const uint4* src = reinterpret_cast<const uint4*>(g_cbB);
        uint4* dst = reinterpret_cast<uint4*>(dsm + OFF_CB);
        const int n16 = (K * ROWB * 2) / 16;
        for (int i = tid; i < n16; i += THREADS) dst[i] = src[i];
    }
    for (int i = tid; i < K; i += THREADS) sC2[i] = g_c2[i];

    // --- per-row: residual -> bf16 padded smem row + exact r2 (R1 pattern) ---
    {
        const int r = tid;
        unsigned int* aU = reinterpret_cast<unsigned int*>(dsm + OFF_A) + r * ROWU;
        float r2 = 0.f;
        if (r < rows) {
            const float4* rr = reinterpret_cast<const float4*>(residual + (size_t)(m0 + r) * DIM);
            float p0 = 0.f, p1 = 0.f, p2 = 0.f, p3 = 0.f;
#pragma unroll
            for (int j = 0; j < 16; j++) {
                float4 v = rr[j];
                p0 += v.x * v.x;
                p1 += v.y * v.y;
                p2 += v.z * v.z;
                p3 += v.w * v.w;
                __nv_bfloat162 h0 = __floats2bfloat162_rn(v.x, v.y);
                __nv_bfloat162 h1 = __floats2bfloat162_rn(v.z, v.w);
                aU[2 * j]     = *reinterpret_cast<unsigned int*>(&h0);
                aU[2 * j + 1] = *reinterpret_cast<unsigned int*>(&h1);
            }
            r2 = (p0 + p1) + (p2 + p3);
        } else {
#pragma unroll
            for (int j = 0; j < 32; j++) aU[j] = 0;
        }
        aU[32] = aU[33] = aU[34] = aU[35] = 0;
        sR2[r]   = r2;
        sRMIN[r] = 0xFF7FFFFFu;     // encf(FLT_MAX)
        sCNT[r]  = 0;
    }
    __syncthreads();

    // --- A fragments (resident for the whole scan): 2 m-tiles x 4 k-chunks ---
    uint32_t a[2][4][4];
#pragma unroll
    for (int mt = 0; mt < 2; mt++) {
        uint32_t ad = sb + OFF_A + (uint32_t)(warp * 32 + mt * 16 + (lane & 15)) * 144u
                    + (uint32_t)((lane >> 4) * 16);
#pragma unroll
        for (int kc = 0; kc < 4; kc++) {
            asm volatile("ldmatrix.sync.aligned.m8n8.x4.shared.b16 {%0,%1,%2,%3}, [%4];"
                : "=r"(a[mt][kc][0]), "=r"(a[mt][kc][1]),
                  "=r"(a[mt][kc][2]), "=r"(a[mt][kc][3])
                : "r"(ad + kc * 32));
        }
    }

    // --- per-slot thresholds: 2B = ||r||*Cmax/32 (2x margin over bf16-rn bound) ---
    const float Cmax = __uint_as_float(g_cmaxU);
    int   rowid[4];
    float th2[4], lim[4];
#pragma unroll
    for (int s = 0; s < 4; s++) {
        int r = warp * 32 + (s >> 1) * 16 + (s & 1) * 8 + (lane >> 2);
        rowid[s] = r;
        th2[s]   = sqrtf(sR2[r]) * Cmax * (1.0f / 32.0f) + 2e-5f;
        lim[s]   = 3.0e38f;
    }

    // --- scan all K codes: 8 codes (1 n-tile) per iteration ---
    uint32_t baddr = sb + OFF_CB + (uint32_t)(lane & 7) * 144u + (uint32_t)(((lane >> 3) & 1) * 16);
    const int NT = K >> 3;
    for (int nt = 0; nt < NT; nt++) {
        uint32_t b[4][2];
#pragma unroll
        for (int kc = 0; kc < 4; kc++) {
            asm volatile("ldmatrix.sync.aligned.m8n8.x2.shared.b16 {%0,%1}, [%2];"
                : "=r"(b[kc][0]), "=r"(b[kc][1]) : "r"(baddr + kc * 32));
        }
        baddr += 8 * 144;

        const int colb = (nt << 3) + ((lane & 3) << 1);
        const float c2a = sC2[colb], c2b = sC2[colb + 1];

#pragma unroll
        for (int mt = 0; mt < 2; mt++) {
            float d0 = 0.f, d1 = 0.f, d2 = 0.f, d3 = 0.f;
#pragma unroll
            for (int kc = 0; kc < 4; kc++) {
                asm volatile(
                    "mma.sync.aligned.m16n8k16.row.col.f32.bf16.bf16.f32 "
                    "{%0,%1,%2,%3}, {%4,%5,%6,%7}, {%8,%9}, {%0,%1,%2,%3};"
                    : "+f"(d0), "+f"(d1), "+f"(d2), "+f"(d3)
                    : "r"(a[mt][kc][0]), "r"(a[mt][kc][1]),
                      "r"(a[mt][kc][2]), "r"(a[mt][kc][3]),
                      "r"(b[kc][0]), "r"(b[kc][1]));
            }
            // s~ = c2 - 2*dot  (r2 dropped: argmin-invariant)
            float s0 = __fmaf_rn(d0, -2.0f, c2a);
            float s1 = __fmaf_rn(d1, -2.0f, c2b);
            float s2 = __fmaf_rn(d2, -2.0f, c2a);
            float s3 = __fmaf_rn(d3, -2.0f, c2b);
            const int sl0 = mt * 2, sl1 = mt * 2 + 1;
            if (s0 <= lim[sl0]) {
                int c = atomicAdd(&sCNT[rowid[sl0]], 1);
                if (c < CAP) sCand[rowid[sl0] * CAP + c] = colb;
                lim[sl0] = fminf(lim[sl0], s0 + th2[sl0]);
            }
            if (s1 <= lim[sl0]) {
                int c = atomicAdd(&sCNT[rowid[sl0]], 1);
                if (c < CAP) sCand[rowid[sl0] * CAP + c] = colb + 1;
                lim[sl0] = fminf(lim[sl0], s1 + th2[sl0]);
            }
            if (s2 <= lim[sl1]) {
                int c = atomicAdd(&sCNT[rowid[sl1]], 1);
                if (c < CAP) sCand[rowid[sl1] * CAP + c] = colb;
                lim[sl1] = fminf(lim[sl1], s2 + th2[sl1]);
            }
            if (s3 <= lim[sl1]) {
                int c = atomicAdd(&sCNT[rowid[sl1]], 1);
                if (c < CAP) sCand[rowid[sl1] * CAP + c] = colb + 1;
                lim[sl1] = fminf(lim[sl1], s3 + th2[sl1]);
            }
        }

        // epoch: share per-row best across the 4 covering lanes (stale reads only loosen)
        if ((nt & 7) == 7) {
#pragma unroll
            for (int s = 0; s < 4; s++) {
                atomicMin(&sRMIN[rowid[s]], encf(lim[s] - th2[s]));
                float g = decf(sRMIN[rowid[s]]);
                lim[s] = fminf(lim[s], g + th2[s]);
            }
        }
    }
    __syncthreads();

    // --- exact phase: R1-proven fp32 arithmetic on the candidate set ---
    const int t = tid;
    if (t < rows) {
        const int cn = sCNT[t];
        const float r2 = sR2[t];
        float r[DIM];
        {
            const float4* rr = reinterpret_cast<const float4*>(residual + (size_t)(m0 + t) * DIM);
#pragma unroll
            for (int j = 0; j < 16; j++) {
                float4 v = rr[j];
                r[4 * j + 0] = v.x; r[4 * j + 1] = v.y;
                r[4 * j + 2] = v.z; r[4 * j + 3] = v.w;
            }
        }
        float best = 3.402823466e+38f;
        int bestK = 0;
        if (cn <= CAP) {
            for (int i = 0; i < cn; i++) {
                int k = sCand[t * CAP + i];
                const float4* c4 = reinterpret_cast<const float4*>(cb + (size_t)k * DIM);
                float a0 = 0.f;
#pragma unroll
                for (int j = 0; j < 16; j++) {
                    float4 v = c4[j];
                    a0 += r[4 * j + 0] * v.x;
                    a0 += r[4 * j + 1] * v.y;
                    a0 += r[4 * j + 2] * v.z;
                    a0 += r[4 * j + 3] * v.w;
                }
                float d = (r2 + sC2[k]) - 2.0f * a0;
                if (d < best || (d == best && k < bestK)) { best = d; bestK = k; }
            }
        } else {
            // overflow emergency path (statistically ~never): full exact scan
            for (int k = 0; k < K; k++) {
                const float4* c4 = reinterpret_cast<const float4*>(cb + (size_t)k * DIM);
                float a0 = 0.f;
#pragma unroll
                for (int j = 0; j < 16; j++) {
                    float4 v = c4[j];
                    a0 += r[4 * j + 0] * v.x;
                    a0 += r[4 * j + 1] * v.y;
                    a0 += r[4 * j + 2] * v.z;
                    a0 += r[4 * j + 3] * v.w;
                }
                float d = (r2 + sC2[k]) - 2.0f * a0;
                if (d < best) { best = d; bestK = k; }
            }
        }
        const int n = m0 + t;
        if (wc) codes[n] = (float)bestK;
        if (wq) {
            const float4* brow = reinterpret_cast<const float4*>(cb + (size_t)bestK * DIM);
            float4* qo = reinterpret_cast<float4*>(qout + (size_t)n * DIM);
#pragma unroll
            for (int j = 0; j < 16; j++) qo[j] = brow[j];
        }
    }
}

// ---------------- launch ----------------
extern "C" void kernel_launch(void* const* d_in, const int* in_sizes, int n_in,
                              void* d_out, int out_size)
{
    const float* residual = (const float*)d_in[0];
    const float* cb       = (const float*)d_in[1];
    const int N = in_sizes[0] / DIM;
    const int K = in_sizes[1] / DIM;

    float* out = (float*)d_out;
    int write_q = 0, write_codes = 0;
    float* qout = out;
    float* codes = out;
    if (out_size >= N * DIM + N) {
        write_q = 1; write_codes = 1;
        codes = out + (size_t)N * DIM;
    } else if (out_size >= N * DIM) {
        write_q = 1;
    } else {
        write_codes = 1;
    }

    cudaFuncSetAttribute(vq_main, cudaFuncAttributeMaxDynamicSharedMemorySize, SMEM_DYN);

    prep_kernel<<<(K + 255) / 256, 256>>>(cb, K);

    int blocks = (N + TM - 1) / TM;
    vq_main<<<blocks, THREADS, SMEM_DYN>>>(residual, cb, qout, codes,
                                           N, K, write_q, write_codes);
}

// round 5
// speedup vs baseline: 9.0751x; 9.0751x over previous
#include <cuda_runtime.h>
#include <cuda_bf16.h>
#include <cstdint>

#define DIM     64
#define KMAX    1024
#define TM      512
#define THREADS 512
#define CAP     16

// ---------------- device globals (prep results) ----------------
__device__ float g_c2[KMAX];
__device__ unsigned int g_cmaxU;   // asuint(max ||c_k||), positive-float monotone
// bf16 codebook, 128B rows, 16B-chunk XOR swizzle: chunk_phys = chunk ^ (k&7)
__device__ __align__(16) unsigned short g_cbB[KMAX * DIM];

// ---------------- smem layout (byte offsets) ----------------
#define OFF_CB    0          // 1024*128 = 131072
#define OFF_A     131072     // 512*128  =  65536
#define OFF_C2    196608     // 1024*4   =   4096
#define OFF_R2    200704     // 512*4    =   2048
#define OFF_CNT   202752     // 512*4    =   2048
#define OFF_CAND  204800     // 512*16*2 =  16384
#define SMEM_DYN  221184

__device__ __forceinline__ uint32_t smem_u32(const void* p) {
    uint32_t a;
    asm("{ .reg .u64 t; cvta.to.shared.u64 t, %1; cvt.u32.u64 %0, t; }"
        : "=r"(a) : "l"(p));
    return a;
}

// ---------------- prep: c2 (R1-exact) + swizzled bf16 codebook + Cmax ----------------
__global__ void prep_kernel(const float* __restrict__ cb, int K) {
    int k = blockIdx.x * blockDim.x + threadIdx.x;
    if (k >= K) return;
    const float4* row = reinterpret_cast<const float4*>(cb + (size_t)k * DIM);
    float vals[DIM];
    float p0 = 0.f, p1 = 0.f, p2 = 0.f, p3 = 0.f;
#pragma unroll
    for (int j = 0; j < 16; j += 4) {
        float4 a = row[j + 0];
        float4 b = row[j + 1];
        float4 c = row[j + 2];
        float4 d = row[j + 3];
        p0 += a.x * a.x + a.y * a.y + a.z * a.z + a.w * a.w;
        p1 += b.x * b.x + b.y * b.y + b.z * b.z + b.w * b.w;
        p2 += c.x * c.x + c.y * c.y + c.z * c.z + c.w * c.w;
        p3 += d.x * d.x + d.y * d.y + d.z * d.z + d.w * d.w;
        vals[4*(j+0)+0]=a.x; vals[4*(j+0)+1]=a.y; vals[4*(j+0)+2]=a.z; vals[4*(j+0)+3]=a.w;
        vals[4*(j+1)+0]=b.x; vals[4*(j+1)+1]=b.y; vals[4*(j+1)+2]=b.z; vals[4*(j+1)+3]=b.w;
        vals[4*(j+2)+0]=c.x; vals[4*(j+2)+1]=c.y; vals[4*(j+2)+2]=c.z; vals[4*(j+2)+3]=c.w;
        vals[4*(j+3)+0]=d.x; vals[4*(j+3)+1]=d.y; vals[4*(j+3)+2]=d.z; vals[4*(j+3)+3]=d.w;
    }
    float c2 = (p0 + p1) + (p2 + p3);
    g_c2[k] = c2;
    atomicMax(&g_cmaxU, __float_as_uint(sqrtf(c2)));
#pragma unroll
    for (int c = 0; c < DIM; c++) {
        __nv_bfloat16 h = __float2bfloat16(vals[c]);
        int phys = (c >> 3) ^ (k & 7);               // 16B chunk swizzle
        g_cbB[(size_t)k * DIM + phys * 8 + (c & 7)] = *reinterpret_cast<unsigned short*>(&h);
    }
}

// ---------------- main: two-pass HMMA (min, then guaranteed-superset collect) ----------------
__global__ __launch_bounds__(THREADS, 1)
void vq_main(const float* __restrict__ residual,
             const float* __restrict__ cb,
             float* __restrict__ qout,
             float* __restrict__ codes,
             int N, int K, int wq, int wc)
{
    extern __shared__ __align__(16) unsigned char dsm[];
    const uint32_t sb = smem_u32(dsm);

    float*          sC2   = (float*)(dsm + OFF_C2);
    float*          sR2   = (float*)(dsm + OFF_R2);
    int*            sCNT  = (int*)(dsm + OFF_CNT);
    unsigned short* sCand = (unsigned short*)(dsm + OFF_CAND);

    const int tid  = threadIdx.x;
    const int lane = tid & 31;
    const int warp = tid >> 5;
    const int m0   = blockIdx.x * TM;
    const int rows = (N - m0 < TM) ? (N - m0) : TM;
    const int NT   = K >> 3;

    // --- stage codebook image (pre-swizzled, identity uint4 copy) ---
    {
        const uint4* src = reinterpret_cast<const uint4*>(g_cbB);
        uint4* dst = reinterpret_cast<uint4*>(dsm + OFF_CB);
        const int n16 = (K * DIM * 2) / 16;
#pragma unroll 4
        for (int i = tid; i < n16; i += THREADS) dst[i] = src[i];
    }
    for (int i = tid; i < K; i += THREADS) sC2[i] = g_c2[i];

    // --- per-row: residual -> bf16 swizzled smem + exact r2 (R1 pattern) ---
    {
        const int r = tid;
        unsigned int* aU = reinterpret_cast<unsigned int*>(dsm + OFF_A) + r * 32;
        float r2 = 0.f;
        if (r < rows) {
            const float4* rr = reinterpret_cast<const float4*>(residual + (size_t)(m0 + r) * DIM);
            float p0 = 0.f, p1 = 0.f, p2 = 0.f, p3 = 0.f;
#pragma unroll
            for (int j = 0; j < 16; j++) {
                float4 v = rr[j];
                p0 += v.x * v.x;
                p1 += v.y * v.y;
                p2 += v.z * v.z;
                p3 += v.w * v.w;
                __nv_bfloat162 h0 = __floats2bfloat162_rn(v.x, v.y);
                __nv_bfloat162 h1 = __floats2bfloat162_rn(v.z, v.w);
                int j0 = 2 * j, j1 = 2 * j + 1;
                aU[(((j0 >> 2) ^ (r & 7)) << 2) + (j0 & 3)] = *reinterpret_cast<unsigned int*>(&h0);
                aU[(((j1 >> 2) ^ (r & 7)) << 2) + (j1 & 3)] = *reinterpret_cast<unsigned int*>(&h1);
            }
            r2 = (p0 + p1) + (p2 + p3);
        } else {
#pragma unroll
            for (int j = 0; j < 32; j++) aU[j] = 0;
        }
        sR2[r]  = r2;
        sCNT[r] = 0;
    }
    __syncthreads();

    // --- A fragments (resident): 2 m-tiles x 4 k-chunks, swizzled ldmatrix.x4 ---
    uint32_t a[2][4][4];
#pragma unroll
    for (int mt = 0; mt < 2; mt++) {
        const uint32_t rowb = (uint32_t)(warp * 32 + mt * 16 + (lane & 15)) * 128u;
#pragma unroll
        for (int kc = 0; kc < 4; kc++) {
            uint32_t phys = (uint32_t)((2 * kc + (lane >> 4)) ^ (lane & 7));
            uint32_t ad = sb + OFF_A + rowb + (phys << 4);
            asm volatile("ldmatrix.sync.aligned.m8n8.x4.shared.b16 {%0,%1,%2,%3}, [%4];"
                : "=r"(a[mt][kc][0]), "=r"(a[mt][kc][1]),
                  "=r"(a[mt][kc][2]), "=r"(a[mt][kc][3])
                : "r"(ad));
        }
    }

    // --- per-lane B base addresses (swizzled; constant + nt*1024) ---
    const uint32_t bb0 = sb + OFF_CB + (uint32_t)(lane & 7) * 128u
                       + ((uint32_t)(((lane >> 3))     ^ (lane & 7)) << 4);
    const uint32_t bb1 = sb + OFF_CB + (uint32_t)(lane & 7) * 128u
                       + ((uint32_t)((4 + (lane >> 3)) ^ (lane & 7)) << 4);
    const float* c2p = sC2 + ((lane & 3) << 1);

    // ================= PASS A: per-row min of s~ = c2 - 2*dot~ =================
    float mA0a = 3.0e38f, mA0b = 3.0e38f, mA1a = 3.0e38f, mA1b = 3.0e38f; // mt0: rowA, rowB
    float mB0a = 3.0e38f, mB0b = 3.0e38f, mB1a = 3.0e38f, mB1b = 3.0e38f; // mt1

#pragma unroll 2
    for (int nt = 0; nt < NT; nt++) {
        uint32_t b[8];
        asm volatile("ldmatrix.sync.aligned.m8n8.x4.shared.b16 {%0,%1,%2,%3}, [%4];"
            : "=r"(b[0]), "=r"(b[1]), "=r"(b[2]), "=r"(b[3]) : "r"(bb0 + nt * 1024));
        asm volatile("ldmatrix.sync.aligned.m8n8.x4.shared.b16 {%0,%1,%2,%3}, [%4];"
            : "=r"(b[4]), "=r"(b[5]), "=r"(b[6]), "=r"(b[7]) : "r"(bb1 + nt * 1024));
        const float2 c2v = *reinterpret_cast<const float2*>(c2p + (nt << 3));
#pragma unroll
        for (int mt = 0; mt < 2; mt++) {
            float d0 = 0.f, d1 = 0.f, d2 = 0.f, d3 = 0.f;
#pragma unroll
            for (int kc = 0; kc < 4; kc++) {
                asm volatile(
                    "mma.sync.aligned.m16n8k16.row.col.f32.bf16.bf16.f32 "
                    "{%0,%1,%2,%3}, {%4,%5,%6,%7}, {%8,%9}, {%0,%1,%2,%3};"
                    : "+f"(d0), "+f"(d1), "+f"(d2), "+f"(d3)
                    : "r"(a[mt][kc][0]), "r"(a[mt][kc][1]),
                      "r"(a[mt][kc][2]), "r"(a[mt][kc][3]),
                      "r"(b[kc * 2]), "r"(b[kc * 2 + 1]));
            }
            float s0 = __fmaf_rn(d0, -2.0f, c2v.x);
            float s1 = __fmaf_rn(d1, -2.0f, c2v.y);
            float s2 = __fmaf_rn(d2, -2.0f, c2v.x);
            float s3 = __fmaf_rn(d3, -2.0f, c2v.y);
            if (mt == 0) {
                mA0a = fminf(mA0a, s0); mA0b = fminf(mA0b, s1);
                mA1a = fminf(mA1a, s2); mA1b = fminf(mA1b, s3);
            } else {
                mB0a = fminf(mB0a, s0); mB0b = fminf(mB0b, s1);
                mB1a = fminf(mB1a, s2); mB1b = fminf(mB1b, s3);
            }
        }
    }

    // --- quad reduce + threshold -> per-slot limits (registers, exact) ---
    const float CmaxC = __uint_as_float(g_cmaxU) * 0.018f;
    float lim[2][2];
    {
        float v00 = fminf(mA0a, mA0b);
        float v01 = fminf(mA1a, mA1b);
        float v10 = fminf(mB0a, mB0b);
        float v11 = fminf(mB1a, mB1b);
        v00 = fminf(v00, __shfl_xor_sync(0xFFFFFFFFu, v00, 1));
        v00 = fminf(v00, __shfl_xor_sync(0xFFFFFFFFu, v00, 2));
        v01 = fminf(v01, __shfl_xor_sync(0xFFFFFFFFu, v01, 1));
        v01 = fminf(v01, __shfl_xor_sync(0xFFFFFFFFu, v01, 2));
        v10 = fminf(v10, __shfl_xor_sync(0xFFFFFFFFu, v10, 1));
        v10 = fminf(v10, __shfl_xor_sync(0xFFFFFFFFu, v10, 2));
        v11 = fminf(v11, __shfl_xor_sync(0xFFFFFFFFu, v11, 1));
        v11 = fminf(v11, __shfl_xor_sync(0xFFFFFFFFu, v11, 2));
        const int rbase = warp * 32 + (lane >> 2);
        lim[0][0] = v00 + (sqrtf(sR2[rbase +  0]) * CmaxC + 5e-5f);
        lim[0][1] = v01 + (sqrtf(sR2[rbase +  8]) * CmaxC + 5e-5f);
        lim[1][0] = v10 + (sqrtf(sR2[rbase + 16]) * CmaxC + 5e-5f);
        lim[1][1] = v11 + (sqrtf(sR2[rbase + 24]) * CmaxC + 5e-5f);
    }

    // ================= PASS B: bitwise replay, collect s~ <= lim =================
    const int rA0 = warp * 32 + (lane >> 2);
#pragma unroll 2
    for (int nt = 0; nt < NT; nt++) {
        uint32_t b[8];
        asm volatile("ldmatrix.sync.aligned.m8n8.x4.shared.b16 {%0,%1,%2,%3}, [%4];"
            : "=r"(b[0]), "=r"(b[1]), "=r"(b[2]), "=r"(b[3]) : "r"(bb0 + nt * 1024));
        asm volatile("ldmatrix.sync.aligned.m8n8.x4.shared.b16 {%0,%1,%2,%3}, [%4];"
            : "=r"(b[4]), "=r"(b[5]), "=r"(b[6]), "=r"(b[7]) : "r"(bb1 + nt * 1024));
        const float2 c2v = *reinterpret_cast<const float2*>(c2p + (nt << 3));
        const int colb = (nt << 3) + ((lane & 3) << 1);
#pragma unroll
        for (int mt = 0; mt < 2; mt++) {
            float d0 = 0.f, d1 = 0.f, d2 = 0.f, d3 = 0.f;
#pragma unroll
            for (int kc = 0; kc < 4; kc++) {
                asm volatile(
                    "mma.sync.aligned.m16n8k16.row.col.f32.bf16.bf16.f32 "
                    "{%0,%1,%2,%3}, {%4,%5,%6,%7}, {%8,%9}, {%0,%1,%2,%3};"
                    : "+f"(d0), "+f"(d1), "+f"(d2), "+f"(d3)
                    : "r"(a[mt][kc][0]), "r"(a[mt][kc][1]),
                      "r"(a[mt][kc][2]), "r"(a[mt][kc][3]),
                      "r"(b[kc * 2]), "r"(b[kc * 2 + 1]));
            }
            float s0 = __fmaf_rn(d0, -2.0f, c2v.x);
            float s1 = __fmaf_rn(d1, -2.0f, c2v.y);
            float s2 = __fmaf_rn(d2, -2.0f, c2v.x);
            float s3 = __fmaf_rn(d3, -2.0f, c2v.y);
            const int rA = rA0 + mt * 16, rB = rA + 8;
            if (s0 <= lim[mt][0]) {
                int c = atomicAdd(&sCNT[rA], 1);
                if (c < CAP) sCand[rA * CAP + c] = (unsigned short)colb;
            }
            if (s1 <= lim[mt][0]) {
                int c = atomicAdd(&sCNT[rA], 1);
                if (c < CAP) sCand[rA * CAP + c] = (unsigned short)(colb + 1);
            }
            if (s2 <= lim[mt][1]) {
                int c = atomicAdd(&sCNT[rB], 1);
                if (c < CAP) sCand[rB * CAP + c] = (unsigned short)colb;
            }
            if (s3 <= lim[mt][1]) {
                int c = atomicAdd(&sCNT[rB], 1);
                if (c < CAP) sCand[rB * CAP + c] = (unsigned short)(colb + 1);
            }
        }
    }
    __syncthreads();

    // ================= exact phase: R1-proven fp32 on candidate set =================
    const int t = tid;
    if (t < rows) {
        const int cn = sCNT[t];
        int bestK;
        if (cn == 1) {
            bestK = sCand[t * CAP];          // unique candidate: must be the argmin
        } else {
            const float r2 = sR2[t];
            float r[DIM];
            const float4* rr = reinterpret_cast<const float4*>(residual + (size_t)(m0 + t) * DIM);
#pragma unroll
            for (int j = 0; j < 16; j++) {
                float4 v = rr[j];
                r[4 * j + 0] = v.x; r[4 * j + 1] = v.y;
                r[4 * j + 2] = v.z; r[4 * j + 3] = v.w;
            }
            float best = 3.402823466e+38f;
            bestK = 0x7FFFFFFF;
            if (cn <= CAP) {
                for (int i = 0; i < cn; i++) {
                    int k = sCand[t * CAP + i];
                    const float4* c4 = reinterpret_cast<const float4*>(cb + (size_t)k * DIM);
                    float a0 = 0.f;
#pragma unroll
                    for (int j = 0; j < 16; j++) {
                        float4 v = c4[j];
                        a0 += r[4 * j + 0] * v.x;
                        a0 += r[4 * j + 1] * v.y;
                        a0 += r[4 * j + 2] * v.z;
                        a0 += r[4 * j + 3] * v.w;
                    }
                    float d = (r2 + sC2[k]) - 2.0f * a0;
                    if (d < best || (d == best && k < bestK)) { best = d; bestK = k; }
                }
            } else {
                for (int k = 0; k < K; k++) {      // should never trigger
                    const float4* c4 = reinterpret_cast<const float4*>(cb + (size_t)k * DIM);
                    float a0 = 0.f;
#pragma unroll
                    for (int j = 0; j < 16; j++) {
                        float4 v = c4[j];
                        a0 += r[4 * j + 0] * v.x;
                        a0 += r[4 * j + 1] * v.y;
                        a0 += r[4 * j + 2] * v.z;
                        a0 += r[4 * j + 3] * v.w;
                    }
                    float d = (r2 + sC2[k]) - 2.0f * a0;
                    if (d < best) { best = d; bestK = k; }
                }
            }
        }
        const int n = m0 + t;
        if (wc) codes[n] = (float)bestK;
        if (wq) {
            const float4* brow = reinterpret_cast<const float4*>(cb + (size_t)bestK * DIM);
            float4* qo = reinterpret_cast<float4*>(qout + (size_t)n * DIM);
#pragma unroll
            for (int j = 0; j < 16; j++) qo[j] = brow[j];
        }
    }
}

// ---------------- launch ----------------
extern "C" void kernel_launch(void* const* d_in, const int* in_sizes, int n_in,
                              void* d_out, int out_size)
{
    const float* residual = (const float*)d_in[0];
    const float* cb       = (const float*)d_in[1];
    const int N = in_sizes[0] / DIM;
    const int K = in_sizes[1] / DIM;

    float* out = (float*)d_out;
    int write_q = 0, write_codes = 0;
    float* qout = out;
    float* codes = out;
    if (out_size >= N * DIM + N) {
        write_q = 1; write_codes = 1;
        codes = out + (size_t)N * DIM;
    } else if (out_size >= N * DIM) {
        write_q = 1;
    } else {
        write_codes = 1;
    }

    cudaFuncSetAttribute(vq_main, cudaFuncAttributeMaxDynamicSharedMemorySize, SMEM_DYN);

    prep_kernel<<<(K + 255) / 256, 256>>>(cb, K);

    int blocks = (N + TM - 1) / TM;
    vq_main<<<blocks, THREADS, SMEM_DYN>>>(residual, cb, qout, codes,
                                           N, K, write_q, write_codes);
}